// round 4
// baseline (speedup 1.0000x reference)
#include <cuda_runtime.h>
#include <math.h>

typedef unsigned long long u64;

// ---------------- problem constants ----------------
#define Hd   200
#define An   2048            // nodes per modality
#define Nn   6144            // total nodes
#define AH   (An*Hd)         // 409600
#define INV_PI 0.31830988618379067f

// ---------------- scratch (static device globals; no allocs) ----------------
__device__ __align__(16) float g_feats [Nn*Hd];
__device__ __align__(16) float g_nrm   [Nn*Hd];
__device__ __align__(16) float g_intra [96*4096];  // 96 blocks of 64x64
__device__ __align__(16) float g_cdot  [3*An];
__device__ __align__(16) float g_dinv  [Nn];
__device__ __align__(16) float g_h     [Nn*Hd];
__device__ __align__(16) float g_h0    [Nn*Hd];
__device__ __align__(16) float g_hi    [Nn*Hd];
__device__ __align__(16) float g_hx    [3*AH];
__device__ __align__(16) float g_z     [6*AH];

__constant__ int c_jtab[6] = {1,2,0,2,0,1}; // partner modality per gate pair

// ---------------- helpers ----------------
__device__ __forceinline__ u64 ffma2(u64 a, u64 b, u64 c) {
    u64 d; asm("fma.rn.f32x2 %0, %1, %2, %3;" : "=l"(d) : "l"(a), "l"(b), "l"(c));
    return d;
}
__device__ __forceinline__ u64 pack2(float x) {
    u64 d; asm("mov.b64 %0, {%1, %1};" : "=l"(d) : "f"(x));
    return d;
}
__device__ __forceinline__ float2 unpk(u64 v) {
    float2 r; asm("mov.b64 {%0, %1}, %2;" : "=f"(r.x), "=f"(r.y) : "l"(v));
    return r;
}
__device__ __forceinline__ unsigned smem_u32(const void* p) {
    return (unsigned)__cvta_generic_to_shared(p);
}
__device__ __forceinline__ void cpasync16(unsigned dst, const void* src) {
    asm volatile("cp.async.cg.shared.global [%0], [%1], 16;" :: "r"(dst), "l"(src));
}
__device__ __forceinline__ float ang_sim(float d) {
    d *= 0.99999f;
    d = fminf(fmaxf(d, -1.f), 1.f);
    return 1.f - acosf(d) * INV_PI;
}

// ---------------- K1: features + row-normalize + cross-modal dots (fused) ----
__global__ void prep_kernel(const float* __restrict__ xa,
                            const float* __restrict__ xv,
                            const float* __restrict__ xt) {
    int w = threadIdx.x >> 5, lane = threadIdx.x & 31;
    int a = blockIdx.x * 8 + w;           // < 2048
    const float* pa = xa + a * Hd;
    const float* pv = xv + a * Hd;
    const float* pt = xt + a * Hd;
    float va[7], vv[7], vt[7];
    float saa = 0.f, svv = 0.f, stt = 0.f, sav = 0.f, sat = 0.f, svt = 0.f;
#pragma unroll
    for (int i = 0; i < 7; i++) {
        int c = lane + i * 32;
        float A = (c < Hd) ? pa[c] : 0.f;
        float V = (c < Hd) ? pv[c] : 0.f;
        float T = (c < Hd) ? pt[c] : 0.f;
        va[i] = A; vv[i] = V; vt[i] = T;
        saa = fmaf(A, A, saa); svv = fmaf(V, V, svv); stt = fmaf(T, T, stt);
        sav = fmaf(A, V, sav); sat = fmaf(A, T, sat); svt = fmaf(V, T, svt);
    }
#pragma unroll
    for (int o = 16; o; o >>= 1) {
        saa += __shfl_xor_sync(0xffffffffu, saa, o);
        svv += __shfl_xor_sync(0xffffffffu, svv, o);
        stt += __shfl_xor_sync(0xffffffffu, stt, o);
        sav += __shfl_xor_sync(0xffffffffu, sav, o);
        sat += __shfl_xor_sync(0xffffffffu, sat, o);
        svt += __shfl_xor_sync(0xffffffffu, svt, o);
    }
    float ra = rsqrtf(saa), rv = rsqrtf(svv), rt = rsqrtf(stt);
#pragma unroll
    for (int i = 0; i < 7; i++) {
        int c = lane + i * 32;
        if (c < Hd) {
            g_feats[(0 * An + a) * Hd + c] = va[i];
            g_feats[(1 * An + a) * Hd + c] = vv[i];
            g_feats[(2 * An + a) * Hd + c] = vt[i];
            g_nrm  [(0 * An + a) * Hd + c] = va[i] * ra;
            g_nrm  [(1 * An + a) * Hd + c] = vv[i] * rv;
            g_nrm  [(2 * An + a) * Hd + c] = vt[i] * rt;
        }
    }
    if (lane == 0) {
        g_cdot[0 * An + a] = ang_sim(sav * ra * rv);
        g_cdot[1 * An + a] = ang_sim(sat * ra * rt);
        g_cdot[2 * An + a] = ang_sim(svt * rv * rt);
    }
}

// ---------------- K2: intra 64x64 gram blocks + degree/dinv (fused) ---------
__global__ void intra_kernel() {
    int mb = blockIdx.x;                  // 0..95
    int m = mb >> 5;
    const float* blk = g_nrm + mb * 64 * Hd;
    __shared__ float s[40][68];           // s[kk][row]
    __shared__ float rs[64];
    int t = threadIdx.x;
    int tx = t & 15, ty = t >> 4;
    if (t < 64) rs[t] = 0.f;
    float acc[4][4] = {};
    for (int h0c = 0; h0c < Hd; h0c += 40) {
        __syncthreads();
#pragma unroll
        for (int k = 0; k < 10; k++) {
            int idx = t + k * 256;        // < 2560
            int r = idx / 40, c = idx % 40;
            s[c][r] = blk[r * Hd + h0c + c];
        }
        __syncthreads();
#pragma unroll 4
        for (int kk = 0; kk < 40; kk++) {
            float a[4], b[4];
#pragma unroll
            for (int ii = 0; ii < 4; ii++) a[ii] = s[kk][ty * 4 + ii];
#pragma unroll
            for (int jj = 0; jj < 4; jj++) b[jj] = s[kk][tx * 4 + jj];
#pragma unroll
            for (int ii = 0; ii < 4; ii++)
#pragma unroll
                for (int jj = 0; jj < 4; jj++)
                    acc[ii][jj] = fmaf(a[ii], b[jj], acc[ii][jj]);
        }
    }
#pragma unroll
    for (int ii = 0; ii < 4; ii++) {
        float rsum = 0.f;
#pragma unroll
        for (int jj = 0; jj < 4; jj++) {
            float v = ang_sim(acc[ii][jj]);
            g_intra[mb * 4096 + (ty * 4 + ii) * 64 + (tx * 4 + jj)] = v;
            rsum += v;
        }
        atomicAdd(&rs[ty * 4 + ii], rsum);
    }
    __syncthreads();
    if (t < 64) {
        int a = (mb & 31) * 64 + t;
        float c0 = g_cdot[a], c1 = g_cdot[An + a], c2 = g_cdot[2 * An + a];
        float ssum = rs[t] + ((m == 0) ? (c0 + c1) : (m == 1) ? (c0 + c2) : (c1 + c2));
        g_dinv[mb * 64 + t] = rsqrtf(ssum);
    }
}

// ---------------- K3: structured adj @ h (2r x 5p x j-split-2, FFMA2) -------
__global__ void __launch_bounds__(256) adjmul_kernel() {
    int mb = blockIdx.x;                      // 0..95
    int m = mb >> 5, b = mb & 31;
    __shared__ float sd[64];
    __shared__ float si[64][65];              // normalized intra block [i][j]
    __shared__ __align__(16) float hs[64][40];// h chunk [j][cc]
    __shared__ __align__(16) u64 red[128][10];
    int t = threadIdx.x;
    if (t < 64) sd[t] = g_dinv[mb * 64 + t];
    __syncthreads();
#pragma unroll
    for (int k = 0; k < 16; k++) {
        int idx = t + k * 256;                // < 4096
        int ii = idx >> 6, jj = idx & 63;
        si[ii][jj] = g_intra[mb * 4096 + idx] * sd[ii] * sd[jj];
    }
    int js = t >> 7;                          // 0/1 (j half)
    int slot = t & 127;
    int rowg = slot >> 2, cgv = slot & 3;     // rowg 0..31, cgv 0..3
    int i0 = rowg * 2, i1 = i0 + 1;
    int jbase = js * 32;
    int rowbase = m * An + b * 64;

    int n0 = (m == 0) ? 1 : 0;
    int n1 = (m == 2) ? 1 : 2;
    int a0 = b * 64 + i0, a1 = a0 + 1;
    float dm0 = g_dinv[m * An + a0], dm1 = g_dinv[m * An + a1];
    float w00 = g_cdot[(m + n0 - 1) * An + a0] * dm0 * g_dinv[n0 * An + a0];
    float w10 = g_cdot[(m + n1 - 1) * An + a0] * dm0 * g_dinv[n1 * An + a0];
    float w01 = g_cdot[(m + n0 - 1) * An + a1] * dm1 * g_dinv[n0 * An + a1];
    float w11 = g_cdot[(m + n1 - 1) * An + a1] * dm1 * g_dinv[n1 * An + a1];
    const float* h0r0 = g_h + (n0 * An + a0) * Hd;
    const float* h1r0 = g_h + (n1 * An + a0) * Hd;
    const float* h0r1 = g_h + (n0 * An + a1) * Hd;
    const float* h1r1 = g_h + (n1 * An + a1) * Hd;

    for (int cc = 0; cc < Hd; cc += 40) {
        __syncthreads();                      // red/hs reuse guard
#pragma unroll
        for (int k = 0; k < 10; k++) {
            int idx = t + k * 256;            // < 2560
            hs[idx / 40][idx % 40] = g_h[(rowbase + idx / 40) * Hd + cc + idx % 40];
        }
        __syncthreads();
        u64 acc0[5] = {}, acc1[5] = {};
#pragma unroll 4
        for (int jo = 0; jo < 32; jo++) {
            int j = jbase + jo;
            u64 pa0 = pack2(si[i0][j]);
            u64 pa1 = pack2(si[i1][j]);
            const u64* hp = reinterpret_cast<const u64*>(&hs[j][cgv * 10]);
#pragma unroll
            for (int q = 0; q < 5; q++) {
                acc0[q] = ffma2(pa0, hp[q], acc0[q]);
                acc1[q] = ffma2(pa1, hp[q], acc1[q]);
            }
        }
        if (js == 1) {
#pragma unroll
            for (int q = 0; q < 5; q++) {
                red[slot][q]     = acc0[q];
                red[slot][q + 5] = acc1[q];
            }
        }
        __syncthreads();
        if (js == 0) {
#pragma unroll
            for (int q = 0; q < 5; q++) {
                int c = cc + cgv * 10 + 2 * q;
                float2 v0 = unpk(acc0[q]); float2 p0 = unpk(red[slot][q]);
                float2 v1 = unpk(acc1[q]); float2 p1 = unpk(red[slot][q + 5]);
                float2 x0 = *(const float2*)&h0r0[c];
                float2 y0 = *(const float2*)&h1r0[c];
                float2 x1 = *(const float2*)&h0r1[c];
                float2 y1 = *(const float2*)&h1r1[c];
                float2 o0, o1;
                o0.x = v0.x + p0.x + w00 * x0.x + w10 * y0.x;
                o0.y = v0.y + p0.y + w00 * x0.y + w10 * y0.y;
                o1.x = v1.x + p1.x + w01 * x1.x + w11 * y1.x;
                o1.y = v1.y + p1.y + w01 * x1.y + w11 * y1.y;
                *(float2*)&g_hi[(rowbase + i0) * Hd + c] = o0;
                *(float2*)&g_hi[(rowbase + i1) * Hd + c] = o1;
            }
        }
    }
}

// ---------------- packed-FMA skinny GEMM: C[M,200] = epi(A[M,K] @ W[K,200]) --
// BM=32, BN=200, 640 threads (20 warps). thread = (row=lane, colgroup=warp),
// 5 col-pairs each. B double-buffered via cp.async, A staged via smem.
// MODE 0: fc0   (K=200, relu+bias, writes g_h AND g_h0)
// MODE 1: conv  (K=400 [hi|h0], gcnii epilogue, writes g_h)
// MODE 2: tm    (K=400 [feats_m|h_m], relu+bias, z=modality, writes g_hx)
// MODE 3: cross (K=600 [hx_i|hx_j|hx_i*hx_j], sigmoid+bias, z=pair, writes g_z)
template<int MODE>
__global__ void __launch_bounds__(640) gemm3(const float* __restrict__ Wg,
                                             const float* __restrict__ biasg,
                                             float beta) {
    constexpr int K = (MODE == 0) ? 200 : ((MODE == 3) ? 600 : 400);
    constexpr int NCH = K / 8;
    const int z = blockIdx.z;
    const float *A0, *A1 = nullptr;
    float *C, *C2 = nullptr;
    const float* bias = nullptr;
    if (MODE == 0)      { A0 = g_feats; C = g_h; C2 = g_h0; bias = biasg; }
    else if (MODE == 1) { A0 = g_hi; A1 = g_h0; C = g_h; }
    else if (MODE == 2) { A0 = g_feats + z * AH; A1 = g_h + z * AH;
                          C = g_hx + z * AH; bias = biasg + z * Hd; }
    else                { int ii = z >> 1; int jj = c_jtab[z];
                          A0 = g_hx + ii * AH; A1 = g_hx + jj * AH;
                          C = g_z + z * AH; bias = biasg + z * Hd; }
    const float* W = Wg + z * K * Hd;

    __shared__ __align__(16) float Bs[2][1600];
    __shared__ float As[2][32][9];            // pad 9 -> conflict-free
    int t = threadIdx.x;
    int lane = t & 31, cg = t >> 5;           // row-in-tile, colgroup 0..19
    int row0 = blockIdx.y * 32;
    int r = row0 + lane;

    u64 acc[5] = {0ull, 0ull, 0ull, 0ull, 0ull};

    unsigned bs0 = smem_u32(&Bs[0][0]), bs1 = smem_u32(&Bs[1][0]);

    auto issueB = [&](int ch, int buf) {
        const float* src = W + ch * 8 * Hd;
        unsigned d = buf ? bs1 : bs0;
        if (t < 400) cpasync16(d + t * 16, src + t * 4);
        asm volatile("cp.async.commit_group;");
    };

    int arow = t >> 3, ak = t & 7;            // valid for t<256
    int agrow = row0 + arow;
    auto loadA = [&](int k0) -> float {
        int k = k0 + ak;
        if (MODE == 0) return A0[agrow * Hd + k];
        if (MODE == 3) {
            if (k < 200)      return A0[agrow * Hd + k];
            else if (k < 400) return A1[agrow * Hd + k - 200];
            else { int kr = k - 400; return A0[agrow * Hd + kr] * A1[agrow * Hd + kr]; }
        }
        return (k < 200) ? A0[agrow * Hd + k] : A1[agrow * Hd + k - 200];
    };

    float aval = 0.f;
    if (t < 256) aval = loadA(0);
    issueB(0, 0);

    for (int ch = 0; ch < NCH; ch++) {
        int buf = ch & 1;
        if (t < 256) As[buf][arow][ak] = aval;
        if (ch + 1 < NCH) {
            issueB(ch + 1, buf ^ 1);
            if (t < 256) aval = loadA((ch + 1) * 8);
            asm volatile("cp.async.wait_group 1;");
        } else {
            asm volatile("cp.async.wait_group 0;");
        }
        __syncthreads();
        const float* fB = &Bs[buf][0];
#pragma unroll
        for (int kk = 0; kk < 8; kk++) {
            u64 pa = pack2(As[buf][lane][kk]);
            const u64* bp = reinterpret_cast<const u64*>(fB + kk * 200 + cg * 10);
#pragma unroll
            for (int q = 0; q < 5; q++) acc[q] = ffma2(pa, bp[q], acc[q]);
        }
        __syncthreads();
    }

    // epilogue: row r, cols cg*10 + 2q
    float omb = 1.f - beta;
#pragma unroll
    for (int q = 0; q < 5; q++) {
        int c = cg * 10 + 2 * q;
        float2 v = unpk(acc[q]);
        if (MODE == 0) {
            float2 bb = *(const float2*)&bias[c];
            v.x = fmaxf(v.x + bb.x, 0.f); v.y = fmaxf(v.y + bb.y, 0.f);
            *(float2*)&C [r * Hd + c] = v;
            *(float2*)&C2[r * Hd + c] = v;
        } else if (MODE == 1) {
            float2 hi = *(const float2*)&g_hi[r * Hd + c];
            float2 h0 = *(const float2*)&g_h0[r * Hd + c];
            float2 o;
            o.x = fmaxf(beta * v.x + omb * (0.9f * hi.x + 0.1f * h0.x), 0.f);
            o.y = fmaxf(beta * v.y + omb * (0.9f * hi.y + 0.1f * h0.y), 0.f);
            *(float2*)&C[r * Hd + c] = o;
        } else if (MODE == 2) {
            float2 bb = *(const float2*)&bias[c];
            v.x = fmaxf(v.x + bb.x, 0.f); v.y = fmaxf(v.y + bb.y, 0.f);
            *(float2*)&C[r * Hd + c] = v;
        } else {
            float2 bb = *(const float2*)&bias[c];
            v.x = 1.f / (1.f + __expf(-(v.x + bb.x)));
            v.y = 1.f / (1.f + __expf(-(v.y + bb.y)));
            *(float2*)&C[r * Hd + c] = v;
        }
    }
}

// ---------------- K4: gated combine + final logits (fused) ----------------
__global__ void joint_kernel(const float* __restrict__ uw,
                             const float* __restrict__ ub,
                             float* __restrict__ out) {
    __shared__ float su[3600];
    __shared__ float sb[6];
    int t = threadIdx.x;
    for (int i = t; i < 3600; i += 256) su[i] = uw[i];
    if (t < 6) sb[t] = ub[t] + ub[6 + t] + ub[12 + t];
    __syncthreads();
    int w = t >> 5, lane = t & 31;
    int a = blockIdx.x * 8 + w;                   // < 2048
    float acc[6] = {};
    const float* hx0 = g_hx + 0 * AH + a * Hd;
    const float* hx1 = g_hx + 1 * AH + a * Hd;
    const float* hx2 = g_hx + 2 * AH + a * Hd;
    const float* zb  = g_z + a * Hd;
    for (int c = lane; c < Hd; c += 32) {
        float x0 = hx0[c], x1 = hx1[c], x2 = hx2[c];
        float z0 = zb[0 * AH + c], z1 = zb[1 * AH + c], z2 = zb[2 * AH + c];
        float z3 = zb[3 * AH + c], z4 = zb[4 * AH + c], z5 = zb[5 * AH + c];
        float o0 = z0 * x0 + (1.f - z0) * x1 + z1 * x0 + (1.f - z1) * x2;
        float o1 = z2 * x1 + (1.f - z2) * x0 + z3 * x1 + (1.f - z3) * x2;
        float o2 = z4 * x2 + (1.f - z4) * x0 + z5 * x2 + (1.f - z5) * x1;
#pragma unroll
        for (int tg = 0; tg < 6; tg++)
            acc[tg] += o0 * su[c * 6 + tg]
                     + o1 * su[1200 + c * 6 + tg]
                     + o2 * su[2400 + c * 6 + tg];
    }
#pragma unroll
    for (int o = 16; o; o >>= 1)
#pragma unroll
        for (int tg = 0; tg < 6; tg++)
            acc[tg] += __shfl_xor_sync(0xffffffffu, acc[tg], o);
    if (lane == 0)
#pragma unroll
        for (int tg = 0; tg < 6; tg++)
            out[a * 6 + tg] = acc[tg] + sb[tg];
}

// ---------------- host launcher ----------------
extern "C" void kernel_launch(void* const* d_in, const int* in_sizes, int n_in,
                              void* d_out, int out_size) {
    const float* x_a     = (const float*)d_in[0];
    const float* x_v     = (const float*)d_in[1];
    const float* x_t     = (const float*)d_in[2];
    const float* fc0_w   = (const float*)d_in[3];
    const float* fc0_b   = (const float*)d_in[4];
    const float* conv_w  = (const float*)d_in[5];
    const float* tm_w    = (const float*)d_in[6];
    const float* tm_b    = (const float*)d_in[7];
    const float* cross_w = (const float*)d_in[8];
    const float* cross_b = (const float*)d_in[9];
    const float* uni_w   = (const float*)d_in[10];
    const float* uni_b   = (const float*)d_in[11];
    float* out = (float*)d_out;

    const float beta0 = 0.40546510810816438f;  // log(1.5)
    const float beta1 = 0.22314355131420976f;  // log(1.25)

    prep_kernel<<<256, 256>>>(x_a, x_v, x_t);
    intra_kernel<<<96, 256>>>();

    gemm3<0><<<dim3(1, 192, 1), 640>>>(fc0_w, fc0_b, 0.f);

    adjmul_kernel<<<96, 256>>>();
    gemm3<1><<<dim3(1, 192, 1), 640>>>(conv_w, nullptr, beta0);
    adjmul_kernel<<<96, 256>>>();
    gemm3<1><<<dim3(1, 192, 1), 640>>>(conv_w + 400 * Hd, nullptr, beta1);

    gemm3<2><<<dim3(1, 64, 3), 640>>>(tm_w, tm_b, 0.f);
    gemm3<3><<<dim3(1, 64, 6), 640>>>(cross_w, cross_b, 0.f);

    joint_kernel<<<256, 256>>>(uni_w, uni_b, out);
}

// round 5
// speedup vs baseline: 1.3782x; 1.3782x over previous
#include <cuda_runtime.h>
#include <math.h>

typedef unsigned long long u64;

// ---------------- problem constants ----------------
#define Hd   200
#define An   2048            // nodes per modality
#define Nn   6144            // total nodes
#define AH   (An*Hd)         // 409600
#define INV_PI 0.31830988618379067f

// ---------------- scratch (static device globals; no allocs) ----------------
__device__ __align__(16) float g_feats [Nn*Hd];
__device__ __align__(16) float g_nrm   [Nn*Hd];
__device__ __align__(16) float g_intra [96*4096];  // 96 blocks of 64x64
__device__ __align__(16) float g_cdot  [3*An];
__device__ __align__(16) float g_dinv  [Nn];
__device__ __align__(16) float g_h     [Nn*Hd];
__device__ __align__(16) float g_h0    [Nn*Hd];
__device__ __align__(16) float g_hi    [Nn*Hd];
__device__ __align__(16) float g_hx    [3*AH];
__device__ __align__(16) float g_z     [6*AH];

__constant__ int c_jtab[6] = {1,2,0,2,0,1}; // partner modality per gate pair

// ---------------- helpers ----------------
__device__ __forceinline__ u64 ffma2(u64 a, u64 b, u64 c) {
    u64 d; asm("fma.rn.f32x2 %0, %1, %2, %3;" : "=l"(d) : "l"(a), "l"(b), "l"(c));
    return d;
}
__device__ __forceinline__ u64 pack2(float x) {
    u64 d; asm("mov.b64 %0, {%1, %1};" : "=l"(d) : "f"(x));
    return d;
}
__device__ __forceinline__ float2 unpk(u64 v) {
    float2 r; asm("mov.b64 {%0, %1}, %2;" : "=f"(r.x), "=f"(r.y) : "l"(v));
    return r;
}
__device__ __forceinline__ unsigned smem_u32(const void* p) {
    return (unsigned)__cvta_generic_to_shared(p);
}
__device__ __forceinline__ void cpasync16(unsigned dst, const void* src) {
    asm volatile("cp.async.cg.shared.global [%0], [%1], 16;" :: "r"(dst), "l"(src));
}
__device__ __forceinline__ float ang_sim(float d) {
    d *= 0.99999f;
    d = fminf(fmaxf(d, -1.f), 1.f);
    return 1.f - acosf(d) * INV_PI;
}

// ---------------- K1: features + row-normalize + cross-modal dots (fused) ----
__global__ void prep_kernel(const float* __restrict__ xa,
                            const float* __restrict__ xv,
                            const float* __restrict__ xt) {
    int w = threadIdx.x >> 5, lane = threadIdx.x & 31;
    int a = blockIdx.x * 8 + w;           // < 2048
    const float* pa = xa + a * Hd;
    const float* pv = xv + a * Hd;
    const float* pt = xt + a * Hd;
    float va[7], vv[7], vt[7];
    float saa = 0.f, svv = 0.f, stt = 0.f, sav = 0.f, sat = 0.f, svt = 0.f;
#pragma unroll
    for (int i = 0; i < 7; i++) {
        int c = lane + i * 32;
        float A = (c < Hd) ? pa[c] : 0.f;
        float V = (c < Hd) ? pv[c] : 0.f;
        float T = (c < Hd) ? pt[c] : 0.f;
        va[i] = A; vv[i] = V; vt[i] = T;
        saa = fmaf(A, A, saa); svv = fmaf(V, V, svv); stt = fmaf(T, T, stt);
        sav = fmaf(A, V, sav); sat = fmaf(A, T, sat); svt = fmaf(V, T, svt);
    }
#pragma unroll
    for (int o = 16; o; o >>= 1) {
        saa += __shfl_xor_sync(0xffffffffu, saa, o);
        svv += __shfl_xor_sync(0xffffffffu, svv, o);
        stt += __shfl_xor_sync(0xffffffffu, stt, o);
        sav += __shfl_xor_sync(0xffffffffu, sav, o);
        sat += __shfl_xor_sync(0xffffffffu, sat, o);
        svt += __shfl_xor_sync(0xffffffffu, svt, o);
    }
    float ra = rsqrtf(saa), rv = rsqrtf(svv), rt = rsqrtf(stt);
#pragma unroll
    for (int i = 0; i < 7; i++) {
        int c = lane + i * 32;
        if (c < Hd) {
            g_feats[(0 * An + a) * Hd + c] = va[i];
            g_feats[(1 * An + a) * Hd + c] = vv[i];
            g_feats[(2 * An + a) * Hd + c] = vt[i];
            g_nrm  [(0 * An + a) * Hd + c] = va[i] * ra;
            g_nrm  [(1 * An + a) * Hd + c] = vv[i] * rv;
            g_nrm  [(2 * An + a) * Hd + c] = vt[i] * rt;
        }
    }
    if (lane == 0) {
        g_cdot[0 * An + a] = ang_sim(sav * ra * rv);
        g_cdot[1 * An + a] = ang_sim(sat * ra * rt);
        g_cdot[2 * An + a] = ang_sim(svt * rv * rt);
    }
}

// ---------------- K2: intra 64x64 gram blocks + degree/dinv (fused) ---------
__global__ void intra_kernel() {
    int mb = blockIdx.x;                  // 0..95
    int m = mb >> 5;
    const float* blk = g_nrm + mb * 64 * Hd;
    __shared__ float s[40][68];           // s[kk][row]
    __shared__ float rs[64];
    int t = threadIdx.x;
    int tx = t & 15, ty = t >> 4;
    if (t < 64) rs[t] = 0.f;
    float acc[4][4] = {};
    for (int h0c = 0; h0c < Hd; h0c += 40) {
        __syncthreads();
#pragma unroll
        for (int k = 0; k < 10; k++) {
            int idx = t + k * 256;        // < 2560
            int r = idx / 40, c = idx % 40;
            s[c][r] = blk[r * Hd + h0c + c];
        }
        __syncthreads();
#pragma unroll 4
        for (int kk = 0; kk < 40; kk++) {
            float a[4], b[4];
#pragma unroll
            for (int ii = 0; ii < 4; ii++) a[ii] = s[kk][ty * 4 + ii];
#pragma unroll
            for (int jj = 0; jj < 4; jj++) b[jj] = s[kk][tx * 4 + jj];
#pragma unroll
            for (int ii = 0; ii < 4; ii++)
#pragma unroll
                for (int jj = 0; jj < 4; jj++)
                    acc[ii][jj] = fmaf(a[ii], b[jj], acc[ii][jj]);
        }
    }
#pragma unroll
    for (int ii = 0; ii < 4; ii++) {
        float rsum = 0.f;
#pragma unroll
        for (int jj = 0; jj < 4; jj++) {
            float v = ang_sim(acc[ii][jj]);
            g_intra[mb * 4096 + (ty * 4 + ii) * 64 + (tx * 4 + jj)] = v;
            rsum += v;
        }
        atomicAdd(&rs[ty * 4 + ii], rsum);
    }
    __syncthreads();
    if (t < 64) {
        int a = (mb & 31) * 64 + t;
        float c0 = g_cdot[a], c1 = g_cdot[An + a], c2 = g_cdot[2 * An + a];
        float ssum = rs[t] + ((m == 0) ? (c0 + c1) : (m == 1) ? (c0 + c2) : (c1 + c2));
        g_dinv[mb * 64 + t] = rsqrtf(ssum);
    }
}

// ---------------- K3: structured adj @ h (4r x 5p, LDS.128 A, col-split) -----
// grid (96, 2), 160 threads. thread: rg = t&15 -> rows rg*4..+3 of the 64-row
// block; cg = t>>4 (0..9) -> cols half*100 + cg*10 .. +9 (5 pairs).
// Gram block is symmetric, so si[j][i] == si[i][j]: no transpose needed.
__global__ void __launch_bounds__(160) adjmul_kernel() {
    int mb = blockIdx.x;                      // 0..95
    int half = blockIdx.y;                    // 0/1 -> cols 0..99 / 100..199
    int m = mb >> 5, b = mb & 31;
    __shared__ float sd[64];
    __shared__ __align__(16) float si[64][68]; // scaled intra (symmetric)
    __shared__ __align__(16) float hs[64][102];// h columns [j][c]
    int t = threadIdx.x;
    if (t < 64) sd[t] = g_dinv[mb * 64 + t];
    __syncthreads();
    for (int idx = t; idx < 4096; idx += 160) {
        int ii = idx >> 6, jj = idx & 63;
        si[ii][jj] = g_intra[mb * 4096 + idx] * sd[ii] * sd[jj];
    }
    int rowbase = m * An + b * 64;
    int cbase = half * 100;
    for (int idx = t; idx < 6400; idx += 160) {
        int j = idx / 100, c = idx - j * 100;
        hs[j][c] = g_h[(rowbase + j) * Hd + cbase + c];
    }
    __syncthreads();

    int rg = t & 15, cg = t >> 4;             // rg 0..15, cg 0..9
    u64 acc[4][5] = {};
#pragma unroll 4
    for (int j = 0; j < 64; j++) {
        float4 a4 = *(const float4*)&si[j][rg * 4];
        u64 p0 = pack2(a4.x), p1 = pack2(a4.y), p2 = pack2(a4.z), p3 = pack2(a4.w);
        const u64* bp = reinterpret_cast<const u64*>(&hs[j][cg * 10]);
#pragma unroll
        for (int q = 0; q < 5; q++) {
            u64 bq = bp[q];
            acc[0][q] = ffma2(p0, bq, acc[0][q]);
            acc[1][q] = ffma2(p1, bq, acc[1][q]);
            acc[2][q] = ffma2(p2, bq, acc[2][q]);
            acc[3][q] = ffma2(p3, bq, acc[3][q]);
        }
    }

    int n0 = (m == 0) ? 1 : 0;
    int n1 = (m == 2) ? 1 : 2;
#pragma unroll
    for (int rr = 0; rr < 4; rr++) {
        int i = rg * 4 + rr;
        int a = b * 64 + i;
        float dm = g_dinv[m * An + a];
        float w0 = g_cdot[(m + n0 - 1) * An + a] * dm * g_dinv[n0 * An + a];
        float w1 = g_cdot[(m + n1 - 1) * An + a] * dm * g_dinv[n1 * An + a];
        const float* h0r = g_h + (n0 * An + a) * Hd;
        const float* h1r = g_h + (n1 * An + a) * Hd;
#pragma unroll
        for (int q = 0; q < 5; q++) {
            int c = cbase + cg * 10 + 2 * q;
            float2 v = unpk(acc[rr][q]);
            float2 x = *(const float2*)&h0r[c];
            float2 y = *(const float2*)&h1r[c];
            float2 o;
            o.x = v.x + w0 * x.x + w1 * y.x;
            o.y = v.y + w0 * x.y + w1 * y.y;
            *(float2*)&g_hi[(rowbase + i) * Hd + c] = o;
        }
    }
}

// ---------------- packed-FMA skinny GEMM: C[M,200] = epi(A[M,K] @ W[K,200]) --
// BM=32, BN=200, 160 threads. thread = 4 rows (LDS.128 from transposed As)
// x 5 col-pairs. B double-buffered via cp.async; A via LDG->STS transposed.
// Per kk: 1 LDS.128 + 5 LDS.64 + 4 pack + 20 FFMA2  (LDS/FFMA2 = 0.3).
// MODE 0: fc0   (K=200, relu+bias, writes g_h AND g_h0)
// MODE 1: conv  (K=400 [hi|h0], gcnii epilogue, writes g_h)
// MODE 2: tm    (K=400 [feats_m|h_m], relu+bias, z=modality, writes g_hx)
// MODE 3: cross (K=600 [hx_i|hx_j|hx_i*hx_j], sigmoid+bias, z=pair, writes g_z)
template<int MODE>
__global__ void __launch_bounds__(160) gemm4(const float* __restrict__ Wg,
                                             const float* __restrict__ biasg,
                                             float beta) {
    constexpr int K = (MODE == 0) ? 200 : ((MODE == 3) ? 600 : 400);
    constexpr int NCH = K / 8;
    const int z = blockIdx.z;
    const float *A0, *A1 = nullptr;
    float *C, *C2 = nullptr;
    const float* bias = nullptr;
    if (MODE == 0)      { A0 = g_feats; C = g_h; C2 = g_h0; bias = biasg; }
    else if (MODE == 1) { A0 = g_hi; A1 = g_h0; C = g_h; }
    else if (MODE == 2) { A0 = g_feats + z * AH; A1 = g_h + z * AH;
                          C = g_hx + z * AH; bias = biasg + z * Hd; }
    else                { int ii = z >> 1; int jj = c_jtab[z];
                          A0 = g_hx + ii * AH; A1 = g_hx + jj * AH;
                          C = g_z + z * AH; bias = biasg + z * Hd; }
    const float* W = Wg + z * K * Hd;

    __shared__ __align__(16) float Bs[2][1600];     // 8 k x 200 cols
    __shared__ __align__(16) float As[2][8][36];    // [kk][row], pad 36
    int t = threadIdx.x;
    int rg = t & 7, cg = t >> 3;              // rg 0..7 (rows rg*4..+3), cg 0..19
    int row0 = blockIdx.y * 32;

    u64 acc[4][5] = {};

    unsigned bs0 = smem_u32(&Bs[0][0]), bs1 = smem_u32(&Bs[1][0]);

    auto issueB = [&](int ch, int buf) {
        const float* src = W + ch * 8 * Hd;
        unsigned d = buf ? bs1 : bs0;
#pragma unroll
        for (int i = 0; i < 3; i++) {
            int idx = t + i * 160;
            if (idx < 400) cpasync16(d + idx * 16, src + idx * 4);
        }
        asm volatile("cp.async.commit_group;");
    };

    // A loader: 256 (row,kk) slots over 160 threads: idx = t and t+160 (t<96)
    auto loadA = [&](int idx, int k0) -> float {
        int rowi = idx >> 3, kk = idx & 7;
        int grow = row0 + rowi;
        int k = k0 + kk;
        if (MODE == 0) return A0[grow * Hd + k];
        if (MODE == 3) {
            if (k < 200)      return A0[grow * Hd + k];
            else if (k < 400) return A1[grow * Hd + k - 200];
            else { int kr = k - 400; return A0[grow * Hd + kr] * A1[grow * Hd + kr]; }
        }
        return (k < 200) ? A0[grow * Hd + k] : A1[grow * Hd + k - 200];
    };

    float av0 = loadA(t, 0);
    float av1 = (t < 96) ? loadA(t + 160, 0) : 0.f;
    issueB(0, 0);

    for (int ch = 0; ch < NCH; ch++) {
        int buf = ch & 1;
        As[buf][t & 7][t >> 3] = av0;
        if (t < 96) As[buf][(t + 160) & 7][(t + 160) >> 3] = av1;
        if (ch + 1 < NCH) {
            issueB(ch + 1, buf ^ 1);
            int k0n = (ch + 1) * 8;
            av0 = loadA(t, k0n);
            if (t < 96) av1 = loadA(t + 160, k0n);
            asm volatile("cp.async.wait_group 1;");
        } else {
            asm volatile("cp.async.wait_group 0;");
        }
        __syncthreads();
        const float* fB = &Bs[buf][0];
#pragma unroll
        for (int kk = 0; kk < 8; kk++) {
            float4 a4 = *(const float4*)&As[buf][kk][rg * 4];
            u64 p0 = pack2(a4.x), p1 = pack2(a4.y), p2 = pack2(a4.z), p3 = pack2(a4.w);
            const u64* bp = reinterpret_cast<const u64*>(fB + kk * 200 + cg * 10);
#pragma unroll
            for (int q = 0; q < 5; q++) {
                u64 bq = bp[q];
                acc[0][q] = ffma2(p0, bq, acc[0][q]);
                acc[1][q] = ffma2(p1, bq, acc[1][q]);
                acc[2][q] = ffma2(p2, bq, acc[2][q]);
                acc[3][q] = ffma2(p3, bq, acc[3][q]);
            }
        }
        __syncthreads();
    }

    // epilogue: rows row0 + rg*4 + rr, cols cg*10 + 2q
    float omb = 1.f - beta;
#pragma unroll
    for (int rr = 0; rr < 4; rr++) {
        int r = row0 + rg * 4 + rr;
#pragma unroll
        for (int q = 0; q < 5; q++) {
            int c = cg * 10 + 2 * q;
            float2 v = unpk(acc[rr][q]);
            if (MODE == 0) {
                float2 bb = *(const float2*)&bias[c];
                v.x = fmaxf(v.x + bb.x, 0.f); v.y = fmaxf(v.y + bb.y, 0.f);
                *(float2*)&C [r * Hd + c] = v;
                *(float2*)&C2[r * Hd + c] = v;
            } else if (MODE == 1) {
                float2 hi = *(const float2*)&g_hi[r * Hd + c];
                float2 h0 = *(const float2*)&g_h0[r * Hd + c];
                float2 o;
                o.x = fmaxf(beta * v.x + omb * (0.9f * hi.x + 0.1f * h0.x), 0.f);
                o.y = fmaxf(beta * v.y + omb * (0.9f * hi.y + 0.1f * h0.y), 0.f);
                *(float2*)&C[r * Hd + c] = o;
            } else if (MODE == 2) {
                float2 bb = *(const float2*)&bias[c];
                v.x = fmaxf(v.x + bb.x, 0.f); v.y = fmaxf(v.y + bb.y, 0.f);
                *(float2*)&C[r * Hd + c] = v;
            } else {
                float2 bb = *(const float2*)&bias[c];
                v.x = 1.f / (1.f + __expf(-(v.x + bb.x)));
                v.y = 1.f / (1.f + __expf(-(v.y + bb.y)));
                *(float2*)&C[r * Hd + c] = v;
            }
        }
    }
}

// ---------------- K4: gated combine + final logits (fused) ----------------
__global__ void joint_kernel(const float* __restrict__ uw,
                             const float* __restrict__ ub,
                             float* __restrict__ out) {
    __shared__ float su[3600];
    __shared__ float sb[6];
    int t = threadIdx.x;
    for (int i = t; i < 3600; i += 256) su[i] = uw[i];
    if (t < 6) sb[t] = ub[t] + ub[6 + t] + ub[12 + t];
    __syncthreads();
    int w = t >> 5, lane = t & 31;
    int a = blockIdx.x * 8 + w;                   // < 2048
    float acc[6] = {};
    const float* hx0 = g_hx + 0 * AH + a * Hd;
    const float* hx1 = g_hx + 1 * AH + a * Hd;
    const float* hx2 = g_hx + 2 * AH + a * Hd;
    const float* zb  = g_z + a * Hd;
    for (int c = lane; c < Hd; c += 32) {
        float x0 = hx0[c], x1 = hx1[c], x2 = hx2[c];
        float z0 = zb[0 * AH + c], z1 = zb[1 * AH + c], z2 = zb[2 * AH + c];
        float z3 = zb[3 * AH + c], z4 = zb[4 * AH + c], z5 = zb[5 * AH + c];
        float o0 = z0 * x0 + (1.f - z0) * x1 + z1 * x0 + (1.f - z1) * x2;
        float o1 = z2 * x1 + (1.f - z2) * x0 + z3 * x1 + (1.f - z3) * x2;
        float o2 = z4 * x2 + (1.f - z4) * x0 + z5 * x2 + (1.f - z5) * x1;
#pragma unroll
        for (int tg = 0; tg < 6; tg++)
            acc[tg] += o0 * su[c * 6 + tg]
                     + o1 * su[1200 + c * 6 + tg]
                     + o2 * su[2400 + c * 6 + tg];
    }
#pragma unroll
    for (int o = 16; o; o >>= 1)
#pragma unroll
        for (int tg = 0; tg < 6; tg++)
            acc[tg] += __shfl_xor_sync(0xffffffffu, acc[tg], o);
    if (lane == 0)
#pragma unroll
        for (int tg = 0; tg < 6; tg++)
            out[a * 6 + tg] = acc[tg] + sb[tg];
}

// ---------------- host launcher ----------------
extern "C" void kernel_launch(void* const* d_in, const int* in_sizes, int n_in,
                              void* d_out, int out_size) {
    const float* x_a     = (const float*)d_in[0];
    const float* x_v     = (const float*)d_in[1];
    const float* x_t     = (const float*)d_in[2];
    const float* fc0_w   = (const float*)d_in[3];
    const float* fc0_b   = (const float*)d_in[4];
    const float* conv_w  = (const float*)d_in[5];
    const float* tm_w    = (const float*)d_in[6];
    const float* tm_b    = (const float*)d_in[7];
    const float* cross_w = (const float*)d_in[8];
    const float* cross_b = (const float*)d_in[9];
    const float* uni_w   = (const float*)d_in[10];
    const float* uni_b   = (const float*)d_in[11];
    float* out = (float*)d_out;

    const float beta0 = 0.40546510810816438f;  // log(1.5)
    const float beta1 = 0.22314355131420976f;  // log(1.25)

    prep_kernel<<<256, 256>>>(x_a, x_v, x_t);
    intra_kernel<<<96, 256>>>();

    gemm4<0><<<dim3(1, 192, 1), 160>>>(fc0_w, fc0_b, 0.f);

    adjmul_kernel<<<dim3(96, 2), 160>>>();
    gemm4<1><<<dim3(1, 192, 1), 160>>>(conv_w, nullptr, beta0);
    adjmul_kernel<<<dim3(96, 2), 160>>>();
    gemm4<1><<<dim3(1, 192, 1), 160>>>(conv_w + 400 * Hd, nullptr, beta1);

    gemm4<2><<<dim3(1, 64, 3), 160>>>(tm_w, tm_b, 0.f);
    gemm4<3><<<dim3(1, 64, 6), 160>>>(cross_w, cross_b, 0.f);

    joint_kernel<<<256, 256>>>(uni_w, uni_b, out);
}